// round 13
// baseline (speedup 1.0000x reference)
#include <cuda_runtime.h>
#include <cuda_fp16.h>
#include <cstdint>

#define NN 1024
#define OUTC 3264
#define LDC 3328            // padded column count (26*128 = 13*256)
#define CG_TOTAL 615
#define TT_TOTAL 179
#define KSTG 64             // K per pipeline stage
#define AROWB 144           // A smem row stride: 64 fp16 = 128B + 16B pad
#define BROWB 528           // B smem row stride: 256 fp16 = 512B + 16B pad
#define ASZ (128 * AROWB)   // 18432
#define BSZ (KSTG * BROWB)  // 33792
#define STAGE (ASZ + BSZ)   // 52224
#define NSTG 3
#define NIT (NN / KSTG)     // 16

__device__ __align__(16) float g_CG[CG_TOTAL];
__device__ __align__(16) __half g_h[(size_t)4 * NN * LDC];
__device__ __align__(16) __half g_connh[(size_t)4 * NN * NN];
__device__ int g_meta[OUTC];
__device__ float g_sumsq[3];

__constant__ int c_l1[15]     = {0,1,2, 0,1,1,1,2,2, 0,1,1,2,2,2};
__constant__ int c_l2[15]     = {0,1,2, 1,0,1,2,1,2, 2,1,2,0,1,2};
__constant__ int c_LL[15]     = {0,0,0, 1,1,1,1,1,1, 2,2,2,2,2,2};
__constant__ int c_cgBase[16] = {0,1,10,35,44,53,80,125,170,245,270,315,390,415,490,615};
__constant__ int c_ttBase[16] = {0,1,4,9,12,21,30,39,54,69,74,89,104,129,154,179};
__constant__ int c_off3[3]    = {0,1,4};
__constant__ double c_fact[8] = {1.0,1.0,2.0,6.0,24.0,120.0,720.0,5040.0};

// ---------------- CG coefficients -------------------------------------------
__device__ double cg_coeff(int l1, int m1, int l2, int m2, int L, int M) {
    if (m1 + m2 != M) return 0.0;
    int dl = l1 > l2 ? l1 - l2 : l2 - l1;
    if (L < dl || L > l1 + l2) return 0.0;
    double pre = sqrt((2.0*L + 1.0) * c_fact[L+l1-l2] * c_fact[L-l1+l2] *
                      c_fact[l1+l2-L] / c_fact[l1+l2+L+1]);
    pre *= sqrt(c_fact[L+M]*c_fact[L-M]*c_fact[l1-m1]*c_fact[l1+m1]*
                c_fact[l2-m2]*c_fact[l2+m2]);
    double s = 0.0;
    for (int k = 0; k <= l1 + l2 - L; ++k) {
        int d1 = l1+l2-L-k, d2 = l1-m1-k, d3 = l2+m2-k, d4 = L-l2+m1+k, d5 = L-l1-m2+k;
        if (d1 < 0 || d2 < 0 || d3 < 0 || d4 < 0 || d5 < 0) continue;
        double term = (k & 1) ? -1.0 : 1.0;
        term /= c_fact[k]*c_fact[d1]*c_fact[d2]*c_fact[d3]*c_fact[d4]*c_fact[d5];
        s += term;
    }
    return pre * s;
}

__global__ void init_kernel() {
    int gtid = blockIdx.x * 1024 + threadIdx.x;
    if (gtid < 3) g_sumsq[gtid] = 0.0f;
    if (gtid < CG_TOTAL) {
        int t = 0;
        while (t < 14 && gtid >= c_cgBase[t+1]) t++;
        int l1 = c_l1[t], l2 = c_l2[t], L = c_LL[t];
        int rel = gtid - c_cgBase[t];
        int nL = 2*L+1, n2 = 2*l2+1;
        int k = rel % nL, j = (rel/nL) % n2, i = rel/(nL*n2);
        g_CG[gtid] = (float)cg_coeff(l1, i-l1, l2, j-l2, L, k-L);
    }
    if (gtid < OUTC) {
        int col = gtid, t, k;
        if (col < 192)        { t = col >> 6;                    k = 0; }
        else if (col < 1344)  { int r = col-192;  k = r/384; t = 3 + ((r%384)>>6); }
        else                  { int r = col-1344; k = r/384; t = 9 + ((r%384)>>6); }
        int l1 = c_l1[t], n1 = 2*l1+1;
        int ttoff = c_ttBase[t] + k*n1;
        int vbase = c_off3[l1]*64;
        g_meta[col] = ttoff | (n1 << 16) | (vbase << 20);
    }
}

// ---------------- conn -> fp16 ----------------------------------------------
__global__ void conv_kernel(const int* __restrict__ conn) {
    size_t i = ((size_t)blockIdx.x * 256 + threadIdx.x) * 4;
    int4 v = *(const int4*)(conn + i);
    __half2 p0, p1;
    p0.x = __float2half((float)v.x); p0.y = __float2half((float)v.y);
    p1.x = __float2half((float)v.z); p1.y = __float2half((float)v.w);
    uint2 o;
    o.x = *reinterpret_cast<uint32_t*>(&p0);
    o.y = *reinterpret_cast<uint32_t*>(&p1);
    *reinterpret_cast<uint2*>(g_connh + i) = o;
}

// ---------------- fused sx + CG product -> g_h[node][col] (fp16) ------------
__global__ void build_kernel(const float* __restrict__ v0,
                             const float* __restrict__ v1,
                             const float* __restrict__ v2,
                             const float* __restrict__ s0,
                             const float* __restrict__ s1,
                             const float* __restrict__ s2) {
    int node = blockIdx.x;
    int tid = threadIdx.x;
    __shared__ float sv[9*64];
    __shared__ float sxl[9];
    __shared__ float tt[TT_TOTAL];

    // phase A: neighbor reduce -> sxl[9]; thread owns neighbor block [4*tid, 4*tid+4)
    {
        float a[9];
        const float4* p0 = (const float4*)(s0 + (size_t)node * NN) + tid;
        const float4* p1 = (const float4*)(s1 + (size_t)node * NN * 3) + tid * 3;
        const float4* p2 = (const float4*)(s2 + (size_t)node * NN * 5) + tid * 5;
        float4 x0 = p0[0];
        a[0] = x0.x + x0.y + x0.z + x0.w;
        float4 u0 = p1[0], u1 = p1[1], u2 = p1[2];
        a[1] = u0.x + u0.w + u1.z + u2.y;
        a[2] = u0.y + u1.x + u1.w + u2.z;
        a[3] = u0.z + u1.y + u2.x + u2.w;
        float4 w0 = p2[0], w1 = p2[1], w2 = p2[2], w3 = p2[3], w4 = p2[4];
        a[4] = w0.x + w1.y + w2.z + w3.w;
        a[5] = w0.y + w1.z + w2.w + w4.x;
        a[6] = w0.z + w1.w + w3.x + w4.y;
        a[7] = w0.w + w2.x + w3.y + w4.z;
        a[8] = w1.x + w2.y + w3.z + w4.w;
#pragma unroll
        for (int q = 0; q < 9; ++q)
#pragma unroll
            for (int o = 16; o; o >>= 1)
                a[q] += __shfl_down_sync(0xFFFFFFFFu, a[q], o);
        if (tid < 9) sxl[tid] = 0.0f;
        __syncthreads();
        if ((tid & 31) == 0)
#pragma unroll
            for (int q = 0; q < 9; ++q) atomicAdd(&sxl[q], a[q]);
    }

    // load vertex features into shared
    for (int t = tid; t < 576; t += 256) {
        float val;
        if (t < 64)       val = v0[(size_t)node*64  + t];
        else if (t < 256) val = v1[(size_t)node*192 + (t-64)];
        else              val = v2[(size_t)node*320 + (t-256)];
        sv[t] = val;
    }
    __syncthreads();

    // phase B: tt[t][k][i] = sum_j CG[t][i][j][k] * sx[l2][j]
    if (tid < TT_TOTAL) {
        int t = 0;
        while (t < 14 && tid >= c_ttBase[t+1]) t++;
        int l1 = c_l1[t], l2 = c_l2[t], L = c_LL[t];
        int n1 = 2*l1+1, n2 = 2*l2+1, nL = 2*L+1;
        int rel = tid - c_ttBase[t];
        int k = rel / n1, i = rel % n1;
        const float* cgp = g_CG + c_cgBase[t] + i*n2*nL + k;
        const float* sxp = sxl + c_off3[l2];
        float acc = 0.0f;
        for (int j = 0; j < n2; ++j) acc += cgp[j*nL] * sxp[j];
        tt[tid] = acc;
    }
    __syncthreads();

    // phase C: per-column contraction, emit fp16
    __half* H = g_h + (size_t)node * LDC;
    for (int col = tid; col < OUTC; col += 256) {
        int m = g_meta[col];
        int ttoff = m & 0xFFFF, n1 = (m >> 16) & 0xF, vbase = m >> 20;
        int c = col & 63;
        const float* ttp = tt + ttoff;
        const float* vp  = sv + vbase + c;
        float acc = 0.0f;
        for (int i = 0; i < n1; ++i) acc += ttp[i] * vp[i*64];
        H[col] = __float2half(acc);
    }
    for (int col = OUTC + tid; col < LDC; col += 256)
        H[col] = __float2half(0.0f);
}

// ---------------- HMMA helpers ----------------------------------------------
__device__ __forceinline__ uint32_t s2u(const void* p) {
    uint32_t a;
    asm("{ .reg .u64 t; cvta.to.shared.u64 t, %1; cvt.u32.u64 %0, t; }" : "=r"(a) : "l"(p));
    return a;
}
__device__ __forceinline__ void cpa16(uint32_t dst, const void* src) {
    asm volatile("cp.async.cg.shared.global [%0], [%1], 16;" :: "r"(dst), "l"(src));
}
__device__ __forceinline__ void ldm4(uint32_t* r, uint32_t a) {
    asm volatile("ldmatrix.sync.aligned.m8n8.x4.shared.b16 {%0,%1,%2,%3}, [%4];"
                 : "=r"(r[0]), "=r"(r[1]), "=r"(r[2]), "=r"(r[3]) : "r"(a));
}
__device__ __forceinline__ void ldm4t(uint32_t* r, uint32_t a) {
    asm volatile("ldmatrix.sync.aligned.m8n8.x4.trans.shared.b16 {%0,%1,%2,%3}, [%4];"
                 : "=r"(r[0]), "=r"(r[1]), "=r"(r[2]), "=r"(r[3]) : "r"(a));
}
__device__ __forceinline__ void mma16816(float* c, const uint32_t* a,
                                         uint32_t b0, uint32_t b1) {
    asm volatile(
        "mma.sync.aligned.m16n8k16.row.col.f32.f16.f16.f32 "
        "{%0,%1,%2,%3}, {%4,%5,%6,%7}, {%8,%9}, {%0,%1,%2,%3};"
        : "+f"(c[0]), "+f"(c[1]), "+f"(c[2]), "+f"(c[3])
        : "r"(a[0]), "r"(a[1]), "r"(a[2]), "r"(a[3]), "r"(b0), "r"(b1));
}

__device__ __forceinline__ void load_stage(
    const __half* __restrict__ Ab,   // conn [row][k], row-major, stride NN
    const __half* __restrict__ Hb,   // cg   [k][col], stride LDC (colBase applied)
    uint32_t sA, int k0, int tid)
{
    const uint32_t sH = sA + ASZ;
    // A: 128 rows x 64 k (128B/row) = 1024 x 16B chunks
#pragma unroll
    for (int i = 0; i < 4; ++i) {
        int c = tid + 256 * i;
        int row = c >> 3, ch = c & 7;
        cpa16(sA + (uint32_t)(row * AROWB + ch * 16),
              Ab + (size_t)row * NN + k0 + ch * 8);
    }
    // B: 64 k-rows x 256 cols (512B/row) = 2048 x 16B chunks
#pragma unroll
    for (int i = 0; i < 8; ++i) {
        int c = tid + 256 * i;
        int row = c >> 5, ch = c & 31;
        cpa16(sH + (uint32_t)(row * BROWB + ch * 16),
              Hb + (size_t)(k0 + row) * LDC + ch * 8);
    }
    asm volatile("cp.async.commit_group;" ::: "memory");
}

// ---------------- GEMM: out = conn @ cg_fp16, fused per-L sumsq --------------
// CTA tile 128x256, warp grid 2(M) x 4(N), warp tile 64x64
__global__ void __launch_bounds__(256, 1)
mma_gemm(float* __restrict__ out) {
    extern __shared__ __align__(256) unsigned char dsm[];
    __shared__ float s_ss[3];
    const uint32_t sb = s2u(dsm);
    const int tid = threadIdx.x, wid = tid >> 5, lane = tid & 31;
    const int wm = wid & 1, wn = wid >> 1;          // 2 x 4 warp grid
    const int b = blockIdx.z, rowBase = blockIdx.y * 128, colBase = blockIdx.x * 256;

    if (tid < 3) s_ss[tid] = 0.0f;

    const __half* Ab = g_connh + ((size_t)(b * NN + rowBase)) * NN;
    const __half* Hb = g_h + ((size_t)b * NN) * LDC + colBase;

    // ldmatrix per-lane byte-offset bases (within a stage buffer)
    const int g = lane >> 3, w = lane & 7;
    const int a_row  = wm * 64 + (g & 1) * 8 + w;
    const int a_colg = (g >> 1) * 8;
    const int b_krow = (g & 1) * 8 + w;
    const int b_ncol = wn * 64 + (g >> 1) * 8;
    uint32_t aoff[4], hoff[4];
#pragma unroll
    for (int mt = 0; mt < 4; ++mt)
        aoff[mt] = (uint32_t)((a_row + mt*16) * AROWB + a_colg * 2);
#pragma unroll
    for (int nt2 = 0; nt2 < 4; ++nt2)
        hoff[nt2] = (uint32_t)(b_krow * BROWB + (b_ncol + nt2*16) * 2);

    float acc[4][8][4];
#pragma unroll
    for (int mt = 0; mt < 4; ++mt)
#pragma unroll
        for (int nt = 0; nt < 8; ++nt)
#pragma unroll
            for (int q = 0; q < 4; ++q) acc[mt][nt][q] = 0.0f;

    load_stage(Ab, Hb, sb + 0 * STAGE, 0, tid);
    load_stage(Ab, Hb, sb + 1 * STAGE, KSTG, tid);

    int buf = 0, nbuf = 2;
    for (int it = 0; it < NIT; ++it) {
        if (it < NIT - 1) {
            asm volatile("cp.async.wait_group 1;" ::: "memory");
        } else {
            asm volatile("cp.async.wait_group 0;" ::: "memory");
        }
        __syncthreads();
        if (it + 2 < NIT) {
            load_stage(Ab, Hb, sb + nbuf * STAGE, (it + 2) * KSTG, tid);
            nbuf = (nbuf + 1 == NSTG) ? 0 : nbuf + 1;
        }

        const uint32_t As = sb + buf * STAGE;
        const uint32_t Hs = As + ASZ;
        buf = (buf + 1 == NSTG) ? 0 : buf + 1;

#pragma unroll
        for (int ks4 = 0; ks4 < 4; ++ks4) {
            uint32_t afr[4][4], hfr[4][4];
#pragma unroll
            for (int mt = 0; mt < 4; ++mt)
                ldm4(afr[mt], As + aoff[mt] + (uint32_t)(ks4 * 32));
#pragma unroll
            for (int nt2 = 0; nt2 < 4; ++nt2)
                ldm4t(hfr[nt2], Hs + hoff[nt2] + (uint32_t)(ks4 * 16 * BROWB));
#pragma unroll
            for (int mt = 0; mt < 4; ++mt)
#pragma unroll
                for (int nt = 0; nt < 8; ++nt) {
                    const int n2 = nt >> 1, p = (nt & 1) * 2;
                    mma16816(acc[mt][nt], afr[mt], hfr[n2][p], hfr[n2][p+1]);
                }
        }
    }
    __syncthreads();

    // epilogue: regs -> global, fused per-L sum of squares
    float ss0 = 0.0f, ss1 = 0.0f, ss2 = 0.0f;
    const int rq = lane >> 2, cq = (lane & 3) * 2;
#pragma unroll
    for (int mt = 0; mt < 4; ++mt) {
#pragma unroll
        for (int nt = 0; nt < 8; ++nt) {
            const int col = colBase + wn * 64 + nt * 8 + cq;
            if (col < OUTC) {
                const int r0 = rowBase + wm * 64 + mt * 16 + rq;
                float* o0 = out + ((size_t)(b * NN) + r0) * OUTC + col;
                float* o1 = o0 + (size_t)8 * OUTC;
                float2 v0 = make_float2(acc[mt][nt][0], acc[mt][nt][1]);
                float2 v1 = make_float2(acc[mt][nt][2], acc[mt][nt][3]);
                float sq = v0.x*v0.x + v0.y*v0.y + v1.x*v1.x + v1.y*v1.y;
                if (col < 192) ss0 += sq; else if (col < 1344) ss1 += sq; else ss2 += sq;
                *(float2*)o0 = v0;
                *(float2*)o1 = v1;
            }
        }
    }
    if (ss0 != 0.0f) atomicAdd(&s_ss[0], ss0);
    if (ss1 != 0.0f) atomicAdd(&s_ss[1], ss1);
    if (ss2 != 0.0f) atomicAdd(&s_ss[2], ss2);
    __syncthreads();
    if (tid < 3 && s_ss[tid] != 0.0f) atomicAdd(&g_sumsq[tid], s_ss[tid]);
}

// ---------------- normalization pass (float4) -------------------------------
__global__ void scale_kernel(float* __restrict__ out) {
    int c4 = blockIdx.x * 256 + threadIdx.x;
    if (c4 >= OUTC / 4) return;
    int col = c4 * 4;
    int node = blockIdx.y;
    int L = (col < 192) ? 0 : (col < 1344) ? 1 : 2;
    float scale = 64.0f / ((float)(2*L + 1) * sqrtf(g_sumsq[L]));
    float4* p = (float4*)(out + (size_t)node * OUTC + col);
    float4 v = *p;
    v.x *= scale; v.y *= scale; v.z *= scale; v.w *= scale;
    *p = v;
}

// ---------------- launch ----------------------------------------------------
extern "C" void kernel_launch(void* const* d_in, const int* in_sizes, int n_in,
                              void* d_out, int out_size) {
    const float* v0 = (const float*)d_in[0];
    const float* v1 = (const float*)d_in[1];
    const float* v2 = (const float*)d_in[2];
    const float* s0 = (const float*)d_in[3];
    const float* s1 = (const float*)d_in[4];
    const float* s2 = (const float*)d_in[5];
    const int* conn = (const int*)d_in[6];
    float* out = (float*)d_out;

    static int smem_set = 0;
    if (!smem_set) {
        cudaFuncSetAttribute(mma_gemm, cudaFuncAttributeMaxDynamicSharedMemorySize,
                             NSTG * STAGE);
        smem_set = 1;
    }

    init_kernel<<<4, 1024>>>();
    conv_kernel<<<4096, 256>>>(conn);
    build_kernel<<<4 * NN, 256>>>(v0, v1, v2, s0, s1, s2);
    mma_gemm<<<dim3(LDC/256, NN/128, 4), 256, NSTG * STAGE>>>(out);
    scale_kernel<<<dim3((OUTC/4 + 255)/256, 4 * NN), 256>>>(out);
}

// round 14
// speedup vs baseline: 1.0910x; 1.0910x over previous
#include <cuda_runtime.h>
#include <cuda_fp16.h>
#include <cstdint>

#define NN 1024
#define OUTC 3264
#define LDC 3328            // padded column count (26*128)
#define CG_TOTAL 615
#define TT_TOTAL 179
#define KSTG 64             // K per pipeline stage
#define AROWB 144           // A smem row stride: 64 fp16 = 128B + 16B pad
#define BROWB 272           // B smem row stride: 128 fp16 = 256B + 16B pad
#define ASZ (128 * AROWB)   // 18432
#define BSZ (KSTG * BROWB)  // 17408
#define STAGE (ASZ + BSZ)   // 35840
#define NSTG 3
#define NIT (NN / KSTG)     // 16

__device__ __align__(16) float g_CG[CG_TOTAL];
__device__ __align__(16) __half g_h[(size_t)4 * NN * LDC];
__device__ __align__(16) __half g_connh[(size_t)4 * NN * NN];
__device__ int g_meta[OUTC];
__device__ float g_sumsq[3];

__constant__ int c_l1[15]     = {0,1,2, 0,1,1,1,2,2, 0,1,1,2,2,2};
__constant__ int c_l2[15]     = {0,1,2, 1,0,1,2,1,2, 2,1,2,0,1,2};
__constant__ int c_LL[15]     = {0,0,0, 1,1,1,1,1,1, 2,2,2,2,2,2};
__constant__ int c_cgBase[16] = {0,1,10,35,44,53,80,125,170,245,270,315,390,415,490,615};
__constant__ int c_ttBase[16] = {0,1,4,9,12,21,30,39,54,69,74,89,104,129,154,179};
__constant__ int c_off3[3]    = {0,1,4};
__constant__ double c_fact[8] = {1.0,1.0,2.0,6.0,24.0,120.0,720.0,5040.0};

// ---------------- CG coefficients -------------------------------------------
__device__ double cg_coeff(int l1, int m1, int l2, int m2, int L, int M) {
    if (m1 + m2 != M) return 0.0;
    int dl = l1 > l2 ? l1 - l2 : l2 - l1;
    if (L < dl || L > l1 + l2) return 0.0;
    double pre = sqrt((2.0*L + 1.0) * c_fact[L+l1-l2] * c_fact[L-l1+l2] *
                      c_fact[l1+l2-L] / c_fact[l1+l2+L+1]);
    pre *= sqrt(c_fact[L+M]*c_fact[L-M]*c_fact[l1-m1]*c_fact[l1+m1]*
                c_fact[l2-m2]*c_fact[l2+m2]);
    double s = 0.0;
    for (int k = 0; k <= l1 + l2 - L; ++k) {
        int d1 = l1+l2-L-k, d2 = l1-m1-k, d3 = l2+m2-k, d4 = L-l2+m1+k, d5 = L-l1-m2+k;
        if (d1 < 0 || d2 < 0 || d3 < 0 || d4 < 0 || d5 < 0) continue;
        double term = (k & 1) ? -1.0 : 1.0;
        term /= c_fact[k]*c_fact[d1]*c_fact[d2]*c_fact[d3]*c_fact[d4]*c_fact[d5];
        s += term;
    }
    return pre * s;
}

__global__ void init_kernel() {
    int gtid = blockIdx.x * 1024 + threadIdx.x;
    if (gtid < 3) g_sumsq[gtid] = 0.0f;
    if (gtid < CG_TOTAL) {
        int t = 0;
        while (t < 14 && gtid >= c_cgBase[t+1]) t++;
        int l1 = c_l1[t], l2 = c_l2[t], L = c_LL[t];
        int rel = gtid - c_cgBase[t];
        int nL = 2*L+1, n2 = 2*l2+1;
        int k = rel % nL, j = (rel/nL) % n2, i = rel/(nL*n2);
        g_CG[gtid] = (float)cg_coeff(l1, i-l1, l2, j-l2, L, k-L);
    }
    if (gtid < OUTC) {
        int col = gtid, t, k;
        if (col < 192)        { t = col >> 6;                    k = 0; }
        else if (col < 1344)  { int r = col-192;  k = r/384; t = 3 + ((r%384)>>6); }
        else                  { int r = col-1344; k = r/384; t = 9 + ((r%384)>>6); }
        int l1 = c_l1[t], n1 = 2*l1+1;
        int ttoff = c_ttBase[t] + k*n1;
        int vbase = c_off3[l1]*64;
        g_meta[col] = ttoff | (n1 << 16) | (vbase << 20);
    }
}

// ---------------- fused conn-conv + sx + CG product -> g_h / g_connh --------
__global__ void build_kernel(const float* __restrict__ v0,
                             const float* __restrict__ v1,
                             const float* __restrict__ v2,
                             const float* __restrict__ s0,
                             const float* __restrict__ s1,
                             const float* __restrict__ s2,
                             const int* __restrict__ conn) {
    int node = blockIdx.x;
    int tid = threadIdx.x;
    __shared__ float sv[9*64];
    __shared__ float sxl[9];
    __shared__ float tt[TT_TOTAL];

    // phase 0: convert this node's conn row (1024 ints) to fp16
    {
        int4 v = *((const int4*)(conn + (size_t)node * NN) + tid);
        __half2 p0, p1;
        p0.x = __float2half((float)v.x); p0.y = __float2half((float)v.y);
        p1.x = __float2half((float)v.z); p1.y = __float2half((float)v.w);
        uint2 o;
        o.x = *reinterpret_cast<uint32_t*>(&p0);
        o.y = *reinterpret_cast<uint32_t*>(&p1);
        *((uint2*)(g_connh + (size_t)node * NN) + tid) = o;
    }

    // phase A: neighbor reduce -> sxl[9]; thread owns neighbor block [4*tid, 4*tid+4)
    {
        float a[9];
        const float4* p0 = (const float4*)(s0 + (size_t)node * NN) + tid;
        const float4* p1 = (const float4*)(s1 + (size_t)node * NN * 3) + tid * 3;
        const float4* p2 = (const float4*)(s2 + (size_t)node * NN * 5) + tid * 5;
        float4 x0 = p0[0];
        a[0] = x0.x + x0.y + x0.z + x0.w;
        float4 u0 = p1[0], u1 = p1[1], u2 = p1[2];
        a[1] = u0.x + u0.w + u1.z + u2.y;
        a[2] = u0.y + u1.x + u1.w + u2.z;
        a[3] = u0.z + u1.y + u2.x + u2.w;
        float4 w0 = p2[0], w1 = p2[1], w2 = p2[2], w3 = p2[3], w4 = p2[4];
        a[4] = w0.x + w1.y + w2.z + w3.w;
        a[5] = w0.y + w1.z + w2.w + w4.x;
        a[6] = w0.z + w1.w + w3.x + w4.y;
        a[7] = w0.w + w2.x + w3.y + w4.z;
        a[8] = w1.x + w2.y + w3.z + w4.w;
#pragma unroll
        for (int q = 0; q < 9; ++q)
#pragma unroll
            for (int o = 16; o; o >>= 1)
                a[q] += __shfl_down_sync(0xFFFFFFFFu, a[q], o);
        if (tid < 9) sxl[tid] = 0.0f;
        __syncthreads();
        if ((tid & 31) == 0)
#pragma unroll
            for (int q = 0; q < 9; ++q) atomicAdd(&sxl[q], a[q]);
    }

    // load vertex features into shared
    for (int t = tid; t < 576; t += 256) {
        float val;
        if (t < 64)       val = v0[(size_t)node*64  + t];
        else if (t < 256) val = v1[(size_t)node*192 + (t-64)];
        else              val = v2[(size_t)node*320 + (t-256)];
        sv[t] = val;
    }
    __syncthreads();

    // phase B: tt[t][k][i] = sum_j CG[t][i][j][k] * sx[l2][j]
    if (tid < TT_TOTAL) {
        int t = 0;
        while (t < 14 && tid >= c_ttBase[t+1]) t++;
        int l1 = c_l1[t], l2 = c_l2[t], L = c_LL[t];
        int n1 = 2*l1+1, n2 = 2*l2+1, nL = 2*L+1;
        int rel = tid - c_ttBase[t];
        int k = rel / n1, i = rel % n1;
        const float* cgp = g_CG + c_cgBase[t] + i*n2*nL + k;
        const float* sxp = sxl + c_off3[l2];
        float acc = 0.0f;
        for (int j = 0; j < n2; ++j) acc += cgp[j*nL] * sxp[j];
        tt[tid] = acc;
    }
    __syncthreads();

    // phase C: per-column-pair contraction, emit half2
    __half2* H2 = (__half2*)(g_h + (size_t)node * LDC);
    for (int c2 = tid; c2 < OUTC/2; c2 += 256) {
        int col0 = c2 * 2;
        float r[2];
#pragma unroll
        for (int u = 0; u < 2; ++u) {
            int col = col0 + u;
            int m = g_meta[col];
            int ttoff = m & 0xFFFF, n1 = (m >> 16) & 0xF, vbase = m >> 20;
            int c = col & 63;
            const float* ttp = tt + ttoff;
            const float* vp  = sv + vbase + c;
            float acc = 0.0f;
            for (int i = 0; i < n1; ++i) acc += ttp[i] * vp[i*64];
            r[u] = acc;
        }
        __half2 h;
        h.x = __float2half(r[0]);
        h.y = __float2half(r[1]);
        H2[c2] = h;
    }
    for (int c2 = OUTC/2 + tid; c2 < LDC/2; c2 += 256)
        H2[c2] = __half2(__float2half(0.0f), __float2half(0.0f));
}

// ---------------- HMMA helpers ----------------------------------------------
__device__ __forceinline__ uint32_t s2u(const void* p) {
    uint32_t a;
    asm("{ .reg .u64 t; cvta.to.shared.u64 t, %1; cvt.u32.u64 %0, t; }" : "=r"(a) : "l"(p));
    return a;
}
__device__ __forceinline__ void cpa16(uint32_t dst, const void* src) {
    asm volatile("cp.async.cg.shared.global [%0], [%1], 16;" :: "r"(dst), "l"(src));
}
__device__ __forceinline__ void ldm4(uint32_t* r, uint32_t a) {
    asm volatile("ldmatrix.sync.aligned.m8n8.x4.shared.b16 {%0,%1,%2,%3}, [%4];"
                 : "=r"(r[0]), "=r"(r[1]), "=r"(r[2]), "=r"(r[3]) : "r"(a));
}
__device__ __forceinline__ void ldm4t(uint32_t* r, uint32_t a) {
    asm volatile("ldmatrix.sync.aligned.m8n8.x4.trans.shared.b16 {%0,%1,%2,%3}, [%4];"
                 : "=r"(r[0]), "=r"(r[1]), "=r"(r[2]), "=r"(r[3]) : "r"(a));
}
__device__ __forceinline__ void mma16816(float* c, const uint32_t* a,
                                         uint32_t b0, uint32_t b1) {
    asm volatile(
        "mma.sync.aligned.m16n8k16.row.col.f32.f16.f16.f32 "
        "{%0,%1,%2,%3}, {%4,%5,%6,%7}, {%8,%9}, {%0,%1,%2,%3};"
        : "+f"(c[0]), "+f"(c[1]), "+f"(c[2]), "+f"(c[3])
        : "r"(a[0]), "r"(a[1]), "r"(a[2]), "r"(a[3]), "r"(b0), "r"(b1));
}

__device__ __forceinline__ void load_stage(
    const __half* __restrict__ Ab,   // conn [row][k], row-major, stride NN
    const __half* __restrict__ Hb,   // cg   [k][col], stride LDC (colBase applied)
    uint32_t sA, int k0, int tid)
{
    const uint32_t sH = sA + ASZ;
    // A: 128 rows x 64 k (128B/row) = 1024 x 16B chunks
#pragma unroll
    for (int i = 0; i < 4; ++i) {
        int c = tid + 256 * i;
        int row = c >> 3, ch = c & 7;
        cpa16(sA + (uint32_t)(row * AROWB + ch * 16),
              Ab + (size_t)row * NN + k0 + ch * 8);
    }
    // B: 64 k-rows x 128 cols (256B/row) = 1024 x 16B chunks
#pragma unroll
    for (int i = 0; i < 4; ++i) {
        int c = tid + 256 * i;
        int row = c >> 4, ch = c & 15;
        cpa16(sH + (uint32_t)(row * BROWB + ch * 16),
              Hb + (size_t)(k0 + row) * LDC + ch * 8);
    }
    asm volatile("cp.async.commit_group;" ::: "memory");
}

// ---------------- GEMM: out = conn @ cg_fp16, fused per-L sumsq --------------
// CTA tile 128x128, warp grid 2(M) x 4(N), warp tile 64x32  (round-12 config)
__global__ void __launch_bounds__(256, 2)
mma_gemm(float* __restrict__ out) {
    extern __shared__ __align__(256) unsigned char dsm[];
    __shared__ float s_ss[3];
    const uint32_t sb = s2u(dsm);
    const int tid = threadIdx.x, wid = tid >> 5, lane = tid & 31;
    const int wm = wid & 1, wn = wid >> 1;          // 2 x 4 warp grid
    const int b = blockIdx.z, rowBase = blockIdx.y * 128, colBase = blockIdx.x * 128;

    if (tid < 3) s_ss[tid] = 0.0f;

    const __half* Ab = g_connh + ((size_t)(b * NN + rowBase)) * NN;
    const __half* Hb = g_h + ((size_t)b * NN) * LDC + colBase;

    // ldmatrix per-lane byte-offset bases (within a stage buffer)
    const int g = lane >> 3, w = lane & 7;
    const int a_row  = wm * 64 + (g & 1) * 8 + w;
    const int a_colg = (g >> 1) * 8;
    const int b_krow = (g & 1) * 8 + w;
    const int b_ncol = wn * 32 + (g >> 1) * 8;
    uint32_t aoff[4], hoff[2];
#pragma unroll
    for (int mt = 0; mt < 4; ++mt)
        aoff[mt] = (uint32_t)((a_row + mt*16) * AROWB + a_colg * 2);
#pragma unroll
    for (int nt2 = 0; nt2 < 2; ++nt2)
        hoff[nt2] = (uint32_t)(b_krow * BROWB + (b_ncol + nt2*16) * 2);

    float acc[4][4][4];
#pragma unroll
    for (int mt = 0; mt < 4; ++mt)
#pragma unroll
        for (int nt = 0; nt < 4; ++nt)
#pragma unroll
            for (int q = 0; q < 4; ++q) acc[mt][nt][q] = 0.0f;

    load_stage(Ab, Hb, sb + 0 * STAGE, 0, tid);
    load_stage(Ab, Hb, sb + 1 * STAGE, KSTG, tid);

    uint32_t afr[2][4][4];   // double-buffered fragments
    uint32_t hfr[2][2][4];

    int buf = 0, nbuf = 2;
    for (int it = 0; it < NIT; ++it) {
        if (it < NIT - 1) {
            asm volatile("cp.async.wait_group 1;" ::: "memory");
        } else {
            asm volatile("cp.async.wait_group 0;" ::: "memory");
        }
        __syncthreads();
        if (it + 2 < NIT) {
            load_stage(Ab, Hb, sb + nbuf * STAGE, (it + 2) * KSTG, tid);
            nbuf = (nbuf + 1 == NSTG) ? 0 : nbuf + 1;
        }

        const uint32_t As = sb + buf * STAGE;
        const uint32_t Hs = As + ASZ;
        buf = (buf + 1 == NSTG) ? 0 : buf + 1;

        // prime fragments for sub-step 0
#pragma unroll
        for (int mt = 0; mt < 4; ++mt) ldm4(afr[0][mt], As + aoff[mt]);
#pragma unroll
        for (int nt2 = 0; nt2 < 2; ++nt2) ldm4t(hfr[0][nt2], Hs + hoff[nt2]);

#pragma unroll
        for (int ks4 = 0; ks4 < 4; ++ks4) {
            const int cur = ks4 & 1, nxt = cur ^ 1;
            if (ks4 < 3) {          // prefetch next sub-step's fragments
#pragma unroll
                for (int mt = 0; mt < 4; ++mt)
                    ldm4(afr[nxt][mt], As + aoff[mt] + (uint32_t)((ks4 + 1) * 32));
#pragma unroll
                for (int nt2 = 0; nt2 < 2; ++nt2)
                    ldm4t(hfr[nxt][nt2], Hs + hoff[nt2] + (uint32_t)((ks4 + 1) * 16 * BROWB));
            }
#pragma unroll
            for (int mt = 0; mt < 4; ++mt)
#pragma unroll
                for (int nt = 0; nt < 4; ++nt) {
                    const int n2 = nt >> 1, p = (nt & 1) * 2;
                    mma16816(acc[mt][nt], afr[cur][mt], hfr[cur][n2][p], hfr[cur][n2][p+1]);
                }
        }
    }
    __syncthreads();

    // epilogue: regs -> global, fused per-L sum of squares
    float ss0 = 0.0f, ss1 = 0.0f, ss2 = 0.0f;
    const int rq = lane >> 2, cq = (lane & 3) * 2;
#pragma unroll
    for (int mt = 0; mt < 4; ++mt) {
#pragma unroll
        for (int nt = 0; nt < 4; ++nt) {
            const int col = colBase + wn * 32 + nt * 8 + cq;
            if (col < OUTC) {
                const int r0 = rowBase + wm * 64 + mt * 16 + rq;
                float* o0 = out + ((size_t)(b * NN) + r0) * OUTC + col;
                float* o1 = o0 + (size_t)8 * OUTC;
                float2 v0 = make_float2(acc[mt][nt][0], acc[mt][nt][1]);
                float2 v1 = make_float2(acc[mt][nt][2], acc[mt][nt][3]);
                float sq = v0.x*v0.x + v0.y*v0.y + v1.x*v1.x + v1.y*v1.y;
                if (col < 192) ss0 += sq; else if (col < 1344) ss1 += sq; else ss2 += sq;
                *(float2*)o0 = v0;
                *(float2*)o1 = v1;
            }
        }
    }
    if (ss0 != 0.0f) atomicAdd(&s_ss[0], ss0);
    if (ss1 != 0.0f) atomicAdd(&s_ss[1], ss1);
    if (ss2 != 0.0f) atomicAdd(&s_ss[2], ss2);
    __syncthreads();
    if (tid < 3 && s_ss[tid] != 0.0f) atomicAdd(&g_sumsq[tid], s_ss[tid]);
}

// ---------------- normalization pass (float4) -------------------------------
__global__ void scale_kernel(float* __restrict__ out) {
    int c4 = blockIdx.x * 256 + threadIdx.x;
    if (c4 >= OUTC / 4) return;
    int col = c4 * 4;
    int node = blockIdx.y;
    int L = (col < 192) ? 0 : (col < 1344) ? 1 : 2;
    float scale = 64.0f / ((float)(2*L + 1) * sqrtf(g_sumsq[L]));
    float4* p = (float4*)(out + (size_t)node * OUTC + col);
    float4 v = *p;
    v.x *= scale; v.y *= scale; v.z *= scale; v.w *= scale;
    *p = v;
}

// ---------------- launch ----------------------------------------------------
extern "C" void kernel_launch(void* const* d_in, const int* in_sizes, int n_in,
                              void* d_out, int out_size) {
    const float* v0 = (const float*)d_in[0];
    const float* v1 = (const float*)d_in[1];
    const float* v2 = (const float*)d_in[2];
    const float* s0 = (const float*)d_in[3];
    const float* s1 = (const float*)d_in[4];
    const float* s2 = (const float*)d_in[5];
    const int* conn = (const int*)d_in[6];
    float* out = (float*)d_out;

    static int smem_set = 0;
    if (!smem_set) {
        cudaFuncSetAttribute(mma_gemm, cudaFuncAttributeMaxDynamicSharedMemorySize,
                             NSTG * STAGE);
        smem_set = 1;
    }

    init_kernel<<<4, 1024>>>();
    build_kernel<<<4 * NN, 256>>>(v0, v1, v2, s0, s1, s2, conn);
    mma_gemm<<<dim3(LDC/128, NN/128, 4), 256, NSTG * STAGE>>>(out);
    scale_kernel<<<dim3((OUTC/4 + 255)/256, 4 * NN), 256>>>(out);
}

// round 15
// speedup vs baseline: 1.1744x; 1.0765x over previous
#include <cuda_runtime.h>
#include <cuda_fp16.h>
#include <cstdint>

#define NN 1024
#define OUTC 3264
#define LDC 3328            // padded column count (26*128)
#define CG_TOTAL 615
#define TT_TOTAL 179
#define KSTG 64             // K per pipeline stage
#define AROWB 144           // A smem row stride: 64 fp16 = 128B + 16B pad
#define BROWB 272           // B smem row stride: 128 fp16 = 256B + 16B pad
#define ASZ (128 * AROWB)   // 18432
#define BSZ (KSTG * BROWB)  // 17408
#define STAGE (ASZ + BSZ)   // 35840
#define NSTG 2
#define NIT (NN / KSTG)     // 16

__device__ __align__(16) float g_CG[CG_TOTAL];
__device__ __align__(16) __half g_h[(size_t)4 * NN * LDC];
__device__ __align__(16) __half g_connh[(size_t)4 * NN * NN];
__device__ int g_meta[OUTC];
__device__ float g_sumsq[3];

__constant__ int c_l1[15]     = {0,1,2, 0,1,1,1,2,2, 0,1,1,2,2,2};
__constant__ int c_l2[15]     = {0,1,2, 1,0,1,2,1,2, 2,1,2,0,1,2};
__constant__ int c_LL[15]     = {0,0,0, 1,1,1,1,1,1, 2,2,2,2,2,2};
__constant__ int c_cgBase[16] = {0,1,10,35,44,53,80,125,170,245,270,315,390,415,490,615};
__constant__ int c_ttBase[16] = {0,1,4,9,12,21,30,39,54,69,74,89,104,129,154,179};
__constant__ int c_off3[3]    = {0,1,4};
__constant__ double c_fact[8] = {1.0,1.0,2.0,6.0,24.0,120.0,720.0,5040.0};

// ---------------- CG coefficients -------------------------------------------
__device__ double cg_coeff(int l1, int m1, int l2, int m2, int L, int M) {
    if (m1 + m2 != M) return 0.0;
    int dl = l1 > l2 ? l1 - l2 : l2 - l1;
    if (L < dl || L > l1 + l2) return 0.0;
    double pre = sqrt((2.0*L + 1.0) * c_fact[L+l1-l2] * c_fact[L-l1+l2] *
                      c_fact[l1+l2-L] / c_fact[l1+l2+L+1]);
    pre *= sqrt(c_fact[L+M]*c_fact[L-M]*c_fact[l1-m1]*c_fact[l1+m1]*
                c_fact[l2-m2]*c_fact[l2+m2]);
    double s = 0.0;
    for (int k = 0; k <= l1 + l2 - L; ++k) {
        int d1 = l1+l2-L-k, d2 = l1-m1-k, d3 = l2+m2-k, d4 = L-l2+m1+k, d5 = L-l1-m2+k;
        if (d1 < 0 || d2 < 0 || d3 < 0 || d4 < 0 || d5 < 0) continue;
        double term = (k & 1) ? -1.0 : 1.0;
        term /= c_fact[k]*c_fact[d1]*c_fact[d2]*c_fact[d3]*c_fact[d4]*c_fact[d5];
        s += term;
    }
    return pre * s;
}

__global__ void init_kernel() {
    int gtid = blockIdx.x * 1024 + threadIdx.x;
    if (gtid < 3) g_sumsq[gtid] = 0.0f;
    if (gtid < CG_TOTAL) {
        int t = 0;
        while (t < 14 && gtid >= c_cgBase[t+1]) t++;
        int l1 = c_l1[t], l2 = c_l2[t], L = c_LL[t];
        int rel = gtid - c_cgBase[t];
        int nL = 2*L+1, n2 = 2*l2+1;
        int k = rel % nL, j = (rel/nL) % n2, i = rel/(nL*n2);
        g_CG[gtid] = (float)cg_coeff(l1, i-l1, l2, j-l2, L, k-L);
    }
    if (gtid < OUTC) {
        int col = gtid, t, k;
        if (col < 192)        { t = col >> 6;                    k = 0; }
        else if (col < 1344)  { int r = col-192;  k = r/384; t = 3 + ((r%384)>>6); }
        else                  { int r = col-1344; k = r/384; t = 9 + ((r%384)>>6); }
        int l1 = c_l1[t], n1 = 2*l1+1;
        int ttoff = c_ttBase[t] + k*n1;
        int vbase = c_off3[l1]*64;
        g_meta[col] = ttoff | (n1 << 16) | (vbase << 20);
    }
}

// ---------------- fused conn-conv + sx + CG product -> g_h / g_connh --------
__global__ void build_kernel(const float* __restrict__ v0,
                             const float* __restrict__ v1,
                             const float* __restrict__ v2,
                             const float* __restrict__ s0,
                             const float* __restrict__ s1,
                             const float* __restrict__ s2,
                             const int* __restrict__ conn) {
    int node = blockIdx.x;
    int tid = threadIdx.x;
    __shared__ float sv[9*64];
    __shared__ float sxl[9];
    __shared__ float tt[TT_TOTAL];

    // phase 0: convert this node's conn row (1024 ints) to fp16
    {
        int4 v = *((const int4*)(conn + (size_t)node * NN) + tid);
        __half2 p0, p1;
        p0.x = __float2half((float)v.x); p0.y = __float2half((float)v.y);
        p1.x = __float2half((float)v.z); p1.y = __float2half((float)v.w);
        uint2 o;
        o.x = *reinterpret_cast<uint32_t*>(&p0);
        o.y = *reinterpret_cast<uint32_t*>(&p1);
        *((uint2*)(g_connh + (size_t)node * NN) + tid) = o;
    }

    // phase A: neighbor reduce -> sxl[9]; thread owns neighbor block [4*tid, 4*tid+4)
    {
        float a[9];
        const float4* p0 = (const float4*)(s0 + (size_t)node * NN) + tid;
        const float4* p1 = (const float4*)(s1 + (size_t)node * NN * 3) + tid * 3;
        const float4* p2 = (const float4*)(s2 + (size_t)node * NN * 5) + tid * 5;
        float4 x0 = p0[0];
        a[0] = x0.x + x0.y + x0.z + x0.w;
        float4 u0 = p1[0], u1 = p1[1], u2 = p1[2];
        a[1] = u0.x + u0.w + u1.z + u2.y;
        a[2] = u0.y + u1.x + u1.w + u2.z;
        a[3] = u0.z + u1.y + u2.x + u2.w;
        float4 w0 = p2[0], w1 = p2[1], w2 = p2[2], w3 = p2[3], w4 = p2[4];
        a[4] = w0.x + w1.y + w2.z + w3.w;
        a[5] = w0.y + w1.z + w2.w + w4.x;
        a[6] = w0.z + w1.w + w3.x + w4.y;
        a[7] = w0.w + w2.x + w3.y + w4.z;
        a[8] = w1.x + w2.y + w3.z + w4.w;
#pragma unroll
        for (int q = 0; q < 9; ++q)
#pragma unroll
            for (int o = 16; o; o >>= 1)
                a[q] += __shfl_down_sync(0xFFFFFFFFu, a[q], o);
        if (tid < 9) sxl[tid] = 0.0f;
        __syncthreads();
        if ((tid & 31) == 0)
#pragma unroll
            for (int q = 0; q < 9; ++q) atomicAdd(&sxl[q], a[q]);
    }

    // load vertex features into shared
    for (int t = tid; t < 576; t += 256) {
        float val;
        if (t < 64)       val = v0[(size_t)node*64  + t];
        else if (t < 256) val = v1[(size_t)node*192 + (t-64)];
        else              val = v2[(size_t)node*320 + (t-256)];
        sv[t] = val;
    }
    __syncthreads();

    // phase B: tt[t][k][i] = sum_j CG[t][i][j][k] * sx[l2][j]
    if (tid < TT_TOTAL) {
        int t = 0;
        while (t < 14 && tid >= c_ttBase[t+1]) t++;
        int l1 = c_l1[t], l2 = c_l2[t], L = c_LL[t];
        int n1 = 2*l1+1, n2 = 2*l2+1, nL = 2*L+1;
        int rel = tid - c_ttBase[t];
        int k = rel / n1, i = rel % n1;
        const float* cgp = g_CG + c_cgBase[t] + i*n2*nL + k;
        const float* sxp = sxl + c_off3[l2];
        float acc = 0.0f;
        for (int j = 0; j < n2; ++j) acc += cgp[j*nL] * sxp[j];
        tt[tid] = acc;
    }
    __syncthreads();

    // phase C: per-column-pair contraction, emit half2
    __half2* H2 = (__half2*)(g_h + (size_t)node * LDC);
    for (int c2 = tid; c2 < OUTC/2; c2 += 256) {
        int col0 = c2 * 2;
        float r[2];
#pragma unroll
        for (int u = 0; u < 2; ++u) {
            int col = col0 + u;
            int m = g_meta[col];
            int ttoff = m & 0xFFFF, n1 = (m >> 16) & 0xF, vbase = m >> 20;
            int c = col & 63;
            const float* ttp = tt + ttoff;
            const float* vp  = sv + vbase + c;
            float acc = 0.0f;
            for (int i = 0; i < n1; ++i) acc += ttp[i] * vp[i*64];
            r[u] = acc;
        }
        __half2 h;
        h.x = __float2half(r[0]);
        h.y = __float2half(r[1]);
        H2[c2] = h;
    }
    for (int c2 = OUTC/2 + tid; c2 < LDC/2; c2 += 256)
        H2[c2] = __half2(__float2half(0.0f), __float2half(0.0f));
}

// ---------------- HMMA helpers ----------------------------------------------
__device__ __forceinline__ uint32_t s2u(const void* p) {
    uint32_t a;
    asm("{ .reg .u64 t; cvta.to.shared.u64 t, %1; cvt.u32.u64 %0, t; }" : "=r"(a) : "l"(p));
    return a;
}
__device__ __forceinline__ void cpa16(uint32_t dst, const void* src) {
    asm volatile("cp.async.cg.shared.global [%0], [%1], 16;" :: "r"(dst), "l"(src));
}
__device__ __forceinline__ void ldm4(uint32_t* r, uint32_t a) {
    asm volatile("ldmatrix.sync.aligned.m8n8.x4.shared.b16 {%0,%1,%2,%3}, [%4];"
                 : "=r"(r[0]), "=r"(r[1]), "=r"(r[2]), "=r"(r[3]) : "r"(a));
}
__device__ __forceinline__ void ldm4t(uint32_t* r, uint32_t a) {
    asm volatile("ldmatrix.sync.aligned.m8n8.x4.trans.shared.b16 {%0,%1,%2,%3}, [%4];"
                 : "=r"(r[0]), "=r"(r[1]), "=r"(r[2]), "=r"(r[3]) : "r"(a));
}
__device__ __forceinline__ void mma16816(float* c, const uint32_t* a,
                                         uint32_t b0, uint32_t b1) {
    asm volatile(
        "mma.sync.aligned.m16n8k16.row.col.f32.f16.f16.f32 "
        "{%0,%1,%2,%3}, {%4,%5,%6,%7}, {%8,%9}, {%0,%1,%2,%3};"
        : "+f"(c[0]), "+f"(c[1]), "+f"(c[2]), "+f"(c[3])
        : "r"(a[0]), "r"(a[1]), "r"(a[2]), "r"(a[3]), "r"(b0), "r"(b1));
}

__device__ __forceinline__ void load_stage(
    const __half* __restrict__ Ab,   // conn [row][k], row-major, stride NN
    const __half* __restrict__ Hb,   // cg   [k][col], stride LDC (colBase applied)
    uint32_t sA, int k0, int tid)
{
    const uint32_t sH = sA + ASZ;
    // A: 128 rows x 64 k (128B/row) = 1024 x 16B chunks, 128 threads
#pragma unroll
    for (int i = 0; i < 8; ++i) {
        int c = tid + 128 * i;
        int row = c >> 3, ch = c & 7;
        cpa16(sA + (uint32_t)(row * AROWB + ch * 16),
              Ab + (size_t)row * NN + k0 + ch * 8);
    }
    // B: 64 k-rows x 128 cols (256B/row) = 1024 x 16B chunks
#pragma unroll
    for (int i = 0; i < 8; ++i) {
        int c = tid + 128 * i;
        int row = c >> 4, ch = c & 15;
        cpa16(sH + (uint32_t)(row * BROWB + ch * 16),
              Hb + (size_t)(k0 + row) * LDC + ch * 8);
    }
    asm volatile("cp.async.commit_group;" ::: "memory");
}

// ---------------- GEMM: out = conn @ cg_fp16, fused per-L sumsq --------------
// CTA = 128 threads, warp grid 2(M) x 2(N), warp tile 64x64, CTA tile 128x128
__global__ void __launch_bounds__(128, 3)
mma_gemm(float* __restrict__ out) {
    extern __shared__ __align__(256) unsigned char dsm[];
    __shared__ float s_ss[3];
    const uint32_t sb = s2u(dsm);
    const int tid = threadIdx.x, wid = tid >> 5, lane = tid & 31;
    const int wm = wid & 1, wn = wid >> 1;          // 2 x 2 warp grid
    const int b = blockIdx.z, rowBase = blockIdx.y * 128, colBase = blockIdx.x * 128;

    if (tid < 3) s_ss[tid] = 0.0f;

    const __half* Ab = g_connh + ((size_t)(b * NN + rowBase)) * NN;
    const __half* Hb = g_h + ((size_t)b * NN) * LDC + colBase;

    // ldmatrix per-lane byte-offset bases (within a stage buffer)
    const int g = lane >> 3, w = lane & 7;
    const int a_row  = wm * 64 + (g & 1) * 8 + w;
    const int a_colg = (g >> 1) * 8;
    const int b_krow = (g & 1) * 8 + w;
    const int b_ncol = wn * 64 + (g >> 1) * 8;
    uint32_t aoff[4], hoff[4];
#pragma unroll
    for (int mt = 0; mt < 4; ++mt)
        aoff[mt] = (uint32_t)((a_row + mt*16) * AROWB + a_colg * 2);
#pragma unroll
    for (int n2 = 0; n2 < 4; ++n2)
        hoff[n2] = (uint32_t)(b_krow * BROWB + (b_ncol + n2*16) * 2);

    float acc[4][8][4];
#pragma unroll
    for (int mt = 0; mt < 4; ++mt)
#pragma unroll
        for (int nt = 0; nt < 8; ++nt)
#pragma unroll
            for (int q = 0; q < 4; ++q) acc[mt][nt][q] = 0.0f;

    load_stage(Ab, Hb, sb, 0, tid);

    for (int it = 0; it < NIT; ++it) {
        const int buf = it & 1;
        if (it < NIT - 1) {
            load_stage(Ab, Hb, sb + (1 - buf) * STAGE, (it + 1) * KSTG, tid);
            asm volatile("cp.async.wait_group 1;" ::: "memory");
        } else {
            asm volatile("cp.async.wait_group 0;" ::: "memory");
        }
        __syncthreads();

        const uint32_t As = sb + buf * STAGE;
        const uint32_t Hs = As + ASZ;
#pragma unroll
        for (int ks4 = 0; ks4 < 4; ++ks4) {
            uint32_t afr[4][4];
#pragma unroll
            for (int mt = 0; mt < 4; ++mt)
                ldm4(afr[mt], As + aoff[mt] + (uint32_t)(ks4 * 32));
#pragma unroll
            for (int n2 = 0; n2 < 4; ++n2) {
                uint32_t hfr[4];
                ldm4t(hfr, Hs + hoff[n2] + (uint32_t)(ks4 * 16 * BROWB));
#pragma unroll
                for (int mt = 0; mt < 4; ++mt) {
                    mma16816(acc[mt][2*n2],   afr[mt], hfr[0], hfr[1]);
                    mma16816(acc[mt][2*n2+1], afr[mt], hfr[2], hfr[3]);
                }
            }
        }
        __syncthreads();
    }

    // epilogue: regs -> global, fused per-L sum of squares
    float ss0 = 0.0f, ss1 = 0.0f, ss2 = 0.0f;
    const int rq = lane >> 2, cq = (lane & 3) * 2;
#pragma unroll
    for (int mt = 0; mt < 4; ++mt) {
#pragma unroll
        for (int nt = 0; nt < 8; ++nt) {
            const int col = colBase + wn * 64 + nt * 8 + cq;
            if (col < OUTC) {
                const int r0 = rowBase + wm * 64 + mt * 16 + rq;
                float* o0 = out + ((size_t)(b * NN) + r0) * OUTC + col;
                float* o1 = o0 + (size_t)8 * OUTC;
                float2 v0 = make_float2(acc[mt][nt][0], acc[mt][nt][1]);
                float2 v1 = make_float2(acc[mt][nt][2], acc[mt][nt][3]);
                float sq = v0.x*v0.x + v0.y*v0.y + v1.x*v1.x + v1.y*v1.y;
                if (col < 192) ss0 += sq; else if (col < 1344) ss1 += sq; else ss2 += sq;
                *(float2*)o0 = v0;
                *(float2*)o1 = v1;
            }
        }
    }
    if (ss0 != 0.0f) atomicAdd(&s_ss[0], ss0);
    if (ss1 != 0.0f) atomicAdd(&s_ss[1], ss1);
    if (ss2 != 0.0f) atomicAdd(&s_ss[2], ss2);
    __syncthreads();
    if (tid < 3 && s_ss[tid] != 0.0f) atomicAdd(&g_sumsq[tid], s_ss[tid]);
}

// ---------------- normalization pass (float4) -------------------------------
__global__ void scale_kernel(float* __restrict__ out) {
    int c4 = blockIdx.x * 256 + threadIdx.x;
    if (c4 >= OUTC / 4) return;
    int col = c4 * 4;
    int node = blockIdx.y;
    int L = (col < 192) ? 0 : (col < 1344) ? 1 : 2;
    float scale = 64.0f / ((float)(2*L + 1) * sqrtf(g_sumsq[L]));
    float4* p = (float4*)(out + (size_t)node * OUTC + col);
    float4 v = *p;
    v.x *= scale; v.y *= scale; v.z *= scale; v.w *= scale;
    *p = v;
}

// ---------------- launch ----------------------------------------------------
extern "C" void kernel_launch(void* const* d_in, const int* in_sizes, int n_in,
                              void* d_out, int out_size) {
    const float* v0 = (const float*)d_in[0];
    const float* v1 = (const float*)d_in[1];
    const float* v2 = (const float*)d_in[2];
    const float* s0 = (const float*)d_in[3];
    const float* s1 = (const float*)d_in[4];
    const float* s2 = (const float*)d_in[5];
    const int* conn = (const int*)d_in[6];
    float* out = (float*)d_out;

    static int smem_set = 0;
    if (!smem_set) {
        cudaFuncSetAttribute(mma_gemm, cudaFuncAttributeMaxDynamicSharedMemorySize,
                             NSTG * STAGE);
        smem_set = 1;
    }

    init_kernel<<<4, 1024>>>();
    build_kernel<<<4 * NN, 256>>>(v0, v1, v2, s0, s1, s2, conn);
    mma_gemm<<<dim3(LDC/128, NN/128, 4), 128, NSTG * STAGE>>>(out);
    scale_kernel<<<dim3((OUTC/4 + 255)/256, 4 * NN), 256>>>(out);
}

// round 17
// speedup vs baseline: 1.2499x; 1.0643x over previous
#include <cuda_runtime.h>
#include <cuda_fp16.h>
#include <cstdint>

#define NN 1024
#define OUTC 3264
#define LDC 3328            // padded column count (26*128)
#define CG_TOTAL 615
#define TT_TOTAL 179
#define KSTG 64             // K per pipeline stage
#define AROWB 144           // A smem row stride: 64 fp16 = 128B + 16B pad
#define BROWB 272           // B smem row stride: 128 fp16 = 256B + 16B pad
#define ASZ (128 * AROWB)   // 18432
#define BSZ (KSTG * BROWB)  // 17408
#define STAGE (ASZ + BSZ)   // 35840
#define NSTG 2
#define NIT (NN / KSTG)     // 16

__device__ __align__(16) float g_CG[CG_TOTAL];
__device__ __align__(16) __half g_h[(size_t)4 * NN * LDC];
__device__ __align__(16) __half g_connh[(size_t)4 * NN * NN];
__device__ __align__(16) __half g_mp[(size_t)4 * NN * OUTC];
__device__ int g_meta[OUTC];
__device__ float g_sumsq[3];

__constant__ int c_l1[15]     = {0,1,2, 0,1,1,1,2,2, 0,1,1,2,2,2};
__constant__ int c_l2[15]     = {0,1,2, 1,0,1,2,1,2, 2,1,2,0,1,2};
__constant__ int c_LL[15]     = {0,0,0, 1,1,1,1,1,1, 2,2,2,2,2,2};
__constant__ int c_cgBase[16] = {0,1,10,35,44,53,80,125,170,245,270,315,390,415,490,615};
__constant__ int c_ttBase[16] = {0,1,4,9,12,21,30,39,54,69,74,89,104,129,154,179};
__constant__ int c_off3[3]    = {0,1,4};
__constant__ float c_fact[8]  = {1.0f,1.0f,2.0f,6.0f,24.0f,120.0f,720.0f,5040.0f};

// ---------------- CG coefficients (fp32, computed on device) -----------------
__device__ float cg_coeff(int l1, int m1, int l2, int m2, int L, int M) {
    if (m1 + m2 != M) return 0.0f;
    int dl = l1 > l2 ? l1 - l2 : l2 - l1;
    if (L < dl || L > l1 + l2) return 0.0f;
    float pre = sqrtf((2.0f*L + 1.0f) * c_fact[L+l1-l2] * c_fact[L-l1+l2] *
                      c_fact[l1+l2-L] / c_fact[l1+l2+L+1]);
    pre *= sqrtf(c_fact[L+M]*c_fact[L-M]*c_fact[l1-m1]*c_fact[l1+m1]*
                 c_fact[l2-m2]*c_fact[l2+m2]);
    float s = 0.0f;
    for (int k = 0; k <= l1 + l2 - L; ++k) {
        int d1 = l1+l2-L-k, d2 = l1-m1-k, d3 = l2+m2-k, d4 = L-l2+m1+k, d5 = L-l1-m2+k;
        if (d1 < 0 || d2 < 0 || d3 < 0 || d4 < 0 || d5 < 0) continue;
        float term = (k & 1) ? -1.0f : 1.0f;
        term /= c_fact[k]*c_fact[d1]*c_fact[d2]*c_fact[d3]*c_fact[d4]*c_fact[d5];
        s += term;
    }
    return pre * s;
}

__global__ void init_kernel() {
    int gtid = blockIdx.x * 1024 + threadIdx.x;
    if (gtid < 3) g_sumsq[gtid] = 0.0f;
    if (gtid < CG_TOTAL) {
        int t = 0;
        while (t < 14 && gtid >= c_cgBase[t+1]) t++;
        int l1 = c_l1[t], l2 = c_l2[t], L = c_LL[t];
        int rel = gtid - c_cgBase[t];
        int nL = 2*L+1, n2 = 2*l2+1;
        int k = rel % nL, j = (rel/nL) % n2, i = rel/(nL*n2);
        g_CG[gtid] = cg_coeff(l1, i-l1, l2, j-l2, L, k-L);
    }
    if (gtid < OUTC) {
        int col = gtid, t, k;
        if (col < 192)        { t = col >> 6;                    k = 0; }
        else if (col < 1344)  { int r = col-192;  k = r/384; t = 3 + ((r%384)>>6); }
        else                  { int r = col-1344; k = r/384; t = 9 + ((r%384)>>6); }
        int l1 = c_l1[t], n1 = 2*l1+1;
        int ttoff = c_ttBase[t] + k*n1;
        int vbase = c_off3[l1]*64;
        g_meta[col] = ttoff | (n1 << 16) | (vbase << 20);
    }
}

// ---------------- fused conn-conv + sx + CG product -> g_h / g_connh --------
__global__ void build_kernel(const float* __restrict__ v0,
                             const float* __restrict__ v1,
                             const float* __restrict__ v2,
                             const float* __restrict__ s0,
                             const float* __restrict__ s1,
                             const float* __restrict__ s2,
                             const int* __restrict__ conn) {
    int node = blockIdx.x;
    int tid = threadIdx.x;
    __shared__ float sv[9*64];
    __shared__ float sxl[9];
    __shared__ float tt[TT_TOTAL];

    // phase 0: convert this node's conn row (1024 ints) to fp16
    {
        int4 v = *((const int4*)(conn + (size_t)node * NN) + tid);
        __half2 p0, p1;
        p0.x = __float2half((float)v.x); p0.y = __float2half((float)v.y);
        p1.x = __float2half((float)v.z); p1.y = __float2half((float)v.w);
        uint2 o;
        o.x = *reinterpret_cast<uint32_t*>(&p0);
        o.y = *reinterpret_cast<uint32_t*>(&p1);
        *((uint2*)(g_connh + (size_t)node * NN) + tid) = o;
    }

    // phase A: neighbor reduce -> sxl[9]; thread owns neighbor block [4*tid, 4*tid+4)
    {
        float a[9];
        const float4* p0 = (const float4*)(s0 + (size_t)node * NN) + tid;
        const float4* p1 = (const float4*)(s1 + (size_t)node * NN * 3) + tid * 3;
        const float4* p2 = (const float4*)(s2 + (size_t)node * NN * 5) + tid * 5;
        float4 x0 = p0[0];
        a[0] = x0.x + x0.y + x0.z + x0.w;
        float4 u0 = p1[0], u1 = p1[1], u2 = p1[2];
        a[1] = u0.x + u0.w + u1.z + u2.y;
        a[2] = u0.y + u1.x + u1.w + u2.z;
        a[3] = u0.z + u1.y + u2.x + u2.w;
        float4 w0 = p2[0], w1 = p2[1], w2 = p2[2], w3 = p2[3], w4 = p2[4];
        a[4] = w0.x + w1.y + w2.z + w3.w;
        a[5] = w0.y + w1.z + w2.w + w4.x;
        a[6] = w0.z + w1.w + w3.x + w4.y;
        a[7] = w0.w + w2.x + w3.y + w4.z;
        a[8] = w1.x + w2.y + w3.z + w4.w;
#pragma unroll
        for (int q = 0; q < 9; ++q)
#pragma unroll
            for (int o = 16; o; o >>= 1)
                a[q] += __shfl_down_sync(0xFFFFFFFFu, a[q], o);
        if (tid < 9) sxl[tid] = 0.0f;
        __syncthreads();
        if ((tid & 31) == 0)
#pragma unroll
            for (int q = 0; q < 9; ++q) atomicAdd(&sxl[q], a[q]);
    }

    // load vertex features into shared
    for (int t = tid; t < 576; t += 256) {
        float val;
        if (t < 64)       val = v0[(size_t)node*64  + t];
        else if (t < 256) val = v1[(size_t)node*192 + (t-64)];
        else              val = v2[(size_t)node*320 + (t-256)];
        sv[t] = val;
    }
    __syncthreads();

    // phase B: tt[t][k][i] = sum_j CG[t][i][j][k] * sx[l2][j]
    if (tid < TT_TOTAL) {
        int t = 0;
        while (t < 14 && tid >= c_ttBase[t+1]) t++;
        int l1 = c_l1[t], l2 = c_l2[t], L = c_LL[t];
        int n1 = 2*l1+1, n2 = 2*l2+1, nL = 2*L+1;
        int rel = tid - c_ttBase[t];
        int k = rel / n1, i = rel % n1;
        const float* cgp = g_CG + c_cgBase[t] + i*n2*nL + k;
        const float* sxp = sxl + c_off3[l2];
        float acc = 0.0f;
        for (int j = 0; j < n2; ++j) acc += cgp[j*nL] * sxp[j];
        tt[tid] = acc;
    }
    __syncthreads();

    // phase C: per-column-pair contraction, emit half2
    __half2* H2 = (__half2*)(g_h + (size_t)node * LDC);
    for (int c2 = tid; c2 < OUTC/2; c2 += 256) {
        int col0 = c2 * 2;
        float r[2];
#pragma unroll
        for (int u = 0; u < 2; ++u) {
            int col = col0 + u;
            int m = g_meta[col];
            int ttoff = m & 0xFFFF, n1 = (m >> 16) & 0xF, vbase = m >> 20;
            int c = col & 63;
            const float* ttp = tt + ttoff;
            const float* vp  = sv + vbase + c;
            float acc = 0.0f;
            for (int i = 0; i < n1; ++i) acc += ttp[i] * vp[i*64];
            r[u] = acc;
        }
        __half2 h;
        h.x = __float2half(r[0]);
        h.y = __float2half(r[1]);
        H2[c2] = h;
    }
    for (int c2 = OUTC/2 + tid; c2 < LDC/2; c2 += 256)
        H2[c2] = __half2(__float2half(0.0f), __float2half(0.0f));
}

// ---------------- HMMA helpers ----------------------------------------------
__device__ __forceinline__ uint32_t s2u(const void* p) {
    uint32_t a;
    asm("{ .reg .u64 t; cvta.to.shared.u64 t, %1; cvt.u32.u64 %0, t; }" : "=r"(a) : "l"(p));
    return a;
}
__device__ __forceinline__ void cpa16(uint32_t dst, const void* src) {
    asm volatile("cp.async.cg.shared.global [%0], [%1], 16;" :: "r"(dst), "l"(src));
}
__device__ __forceinline__ void ldm4(uint32_t* r, uint32_t a) {
    asm volatile("ldmatrix.sync.aligned.m8n8.x4.shared.b16 {%0,%1,%2,%3}, [%4];"
                 : "=r"(r[0]), "=r"(r[1]), "=r"(r[2]), "=r"(r[3]) : "r"(a));
}
__device__ __forceinline__ void ldm4t(uint32_t* r, uint32_t a) {
    asm volatile("ldmatrix.sync.aligned.m8n8.x4.trans.shared.b16 {%0,%1,%2,%3}, [%4];"
                 : "=r"(r[0]), "=r"(r[1]), "=r"(r[2]), "=r"(r[3]) : "r"(a));
}
__device__ __forceinline__ void mma16816(float* c, const uint32_t* a,
                                         uint32_t b0, uint32_t b1) {
    asm volatile(
        "mma.sync.aligned.m16n8k16.row.col.f32.f16.f16.f32 "
        "{%0,%1,%2,%3}, {%4,%5,%6,%7}, {%8,%9}, {%0,%1,%2,%3};"
        : "+f"(c[0]), "+f"(c[1]), "+f"(c[2]), "+f"(c[3])
        : "r"(a[0]), "r"(a[1]), "r"(a[2]), "r"(a[3]), "r"(b0), "r"(b1));
}

__device__ __forceinline__ void load_stage(
    const __half* __restrict__ Ab,   // conn [row][k], row-major, stride NN
    const __half* __restrict__ Hb,   // cg   [k][col], stride LDC (colBase applied)
    uint32_t sA, int k0, int tid)
{
    const uint32_t sH = sA + ASZ;
    // A: 128 rows x 64 k (128B/row) = 1024 x 16B chunks, 128 threads
#pragma unroll
    for (int i = 0; i < 8; ++i) {
        int c = tid + 128 * i;
        int row = c >> 3, ch = c & 7;
        cpa16(sA + (uint32_t)(row * AROWB + ch * 16),
              Ab + (size_t)row * NN + k0 + ch * 8);
    }
    // B: 64 k-rows x 128 cols (256B/row) = 1024 x 16B chunks
#pragma unroll
    for (int i = 0; i < 8; ++i) {
        int c = tid + 128 * i;
        int row = c >> 4, ch = c & 15;
        cpa16(sH + (uint32_t)(row * BROWB + ch * 16),
              Hb + (size_t)(k0 + row) * LDC + ch * 8);
    }
    asm volatile("cp.async.commit_group;" ::: "memory");
}

// ---------------- GEMM: mp = conn @ cg_fp16, fused per-L sumsq ---------------
// CTA = 128 threads, warp grid 2(M) x 2(N), warp tile 64x64, CTA tile 128x128
__global__ void __launch_bounds__(128, 3)
mma_gemm() {
    extern __shared__ __align__(256) unsigned char dsm[];
    __shared__ float s_ss[3];
    const uint32_t sb = s2u(dsm);
    const int tid = threadIdx.x, wid = tid >> 5, lane = tid & 31;
    const int wm = wid & 1, wn = wid >> 1;          // 2 x 2 warp grid
    const int b = blockIdx.z, rowBase = blockIdx.y * 128, colBase = blockIdx.x * 128;

    if (tid < 3) s_ss[tid] = 0.0f;

    const __half* Ab = g_connh + ((size_t)(b * NN + rowBase)) * NN;
    const __half* Hb = g_h + ((size_t)b * NN) * LDC + colBase;

    // ldmatrix per-lane byte-offset bases (within a stage buffer)
    const int g = lane >> 3, w = lane & 7;
    const int a_row  = wm * 64 + (g & 1) * 8 + w;
    const int a_colg = (g >> 1) * 8;
    const int b_krow = (g & 1) * 8 + w;
    const int b_ncol = wn * 64 + (g >> 1) * 8;
    uint32_t aoff[4], hoff[4];
#pragma unroll
    for (int mt = 0; mt < 4; ++mt)
        aoff[mt] = (uint32_t)((a_row + mt*16) * AROWB + a_colg * 2);
#pragma unroll
    for (int n2 = 0; n2 < 4; ++n2)
        hoff[n2] = (uint32_t)(b_krow * BROWB + (b_ncol + n2*16) * 2);

    float acc[4][8][4];
#pragma unroll
    for (int mt = 0; mt < 4; ++mt)
#pragma unroll
        for (int nt = 0; nt < 8; ++nt)
#pragma unroll
            for (int q = 0; q < 4; ++q) acc[mt][nt][q] = 0.0f;

    load_stage(Ab, Hb, sb, 0, tid);

    for (int it = 0; it < NIT; ++it) {
        const int buf = it & 1;
        if (it < NIT - 1) {
            load_stage(Ab, Hb, sb + (1 - buf) * STAGE, (it + 1) * KSTG, tid);
            asm volatile("cp.async.wait_group 1;" ::: "memory");
        } else {
            asm volatile("cp.async.wait_group 0;" ::: "memory");
        }
        __syncthreads();

        const uint32_t As = sb + buf * STAGE;
        const uint32_t Hs = As + ASZ;
#pragma unroll
        for (int ks4 = 0; ks4 < 4; ++ks4) {
            uint32_t afr[4][4];
#pragma unroll
            for (int mt = 0; mt < 4; ++mt)
                ldm4(afr[mt], As + aoff[mt] + (uint32_t)(ks4 * 32));
#pragma unroll
            for (int n2 = 0; n2 < 4; ++n2) {
                uint32_t hfr[4];
                ldm4t(hfr, Hs + hoff[n2] + (uint32_t)(ks4 * 16 * BROWB));
#pragma unroll
                for (int mt = 0; mt < 4; ++mt) {
                    mma16816(acc[mt][2*n2],   afr[mt], hfr[0], hfr[1]);
                    mma16816(acc[mt][2*n2+1], afr[mt], hfr[2], hfr[3]);
                }
            }
        }
        __syncthreads();
    }

    // epilogue: regs -> fp16 scratch, fused per-L sum of squares (fp32)
    float ss0 = 0.0f, ss1 = 0.0f, ss2 = 0.0f;
    const int rq = lane >> 2, cq = (lane & 3) * 2;
#pragma unroll
    for (int mt = 0; mt < 4; ++mt) {
#pragma unroll
        for (int nt = 0; nt < 8; ++nt) {
            const int col = colBase + wn * 64 + nt * 8 + cq;
            if (col < OUTC) {
                const int r0 = rowBase + wm * 64 + mt * 16 + rq;
                __half* o0 = g_mp + ((size_t)(b * NN) + r0) * OUTC + col;
                __half* o1 = o0 + (size_t)8 * OUTC;
                float v0 = acc[mt][nt][0], v1 = acc[mt][nt][1];
                float v2 = acc[mt][nt][2], v3 = acc[mt][nt][3];
                float sq = v0*v0 + v1*v1 + v2*v2 + v3*v3;
                if (col < 192) ss0 += sq; else if (col < 1344) ss1 += sq; else ss2 += sq;
                __half2 h0; h0.x = __float2half(v0); h0.y = __float2half(v1);
                __half2 h1; h1.x = __float2half(v2); h1.y = __float2half(v3);
                *(__half2*)o0 = h0;
                *(__half2*)o1 = h1;
            }
        }
    }
    if (ss0 != 0.0f) atomicAdd(&s_ss[0], ss0);
    if (ss1 != 0.0f) atomicAdd(&s_ss[1], ss1);
    if (ss2 != 0.0f) atomicAdd(&s_ss[2], ss2);
    __syncthreads();
    if (tid < 3 && s_ss[tid] != 0.0f) atomicAdd(&g_sumsq[tid], s_ss[tid]);
}

// ---------------- normalization: fp16 scratch -> fp32 out (float4) ----------
__global__ void scale_kernel(float* __restrict__ out) {
    int c4 = blockIdx.x * 256 + threadIdx.x;
    if (c4 >= OUTC / 4) return;
    int col = c4 * 4;
    int node = blockIdx.y;
    int L = (col < 192) ? 0 : (col < 1344) ? 1 : 2;
    float scale = 64.0f * rsqrtf(g_sumsq[L]) / (float)(2*L + 1);
    const __half2* mp2 = (const __half2*)(g_mp + (size_t)node * OUTC);
    __half2 h01 = mp2[c4 * 2];
    __half2 h23 = mp2[c4 * 2 + 1];
    float4 v;
    v.x = __half2float(h01.x) * scale;
    v.y = __half2float(h01.y) * scale;
    v.z = __half2float(h23.x) * scale;
    v.w = __half2float(h23.y) * scale;
    *(float4*)(out + (size_t)node * OUTC + col) = v;
}

// ---------------- launch ----------------------------------------------------
extern "C" void kernel_launch(void* const* d_in, const int* in_sizes, int n_in,
                              void* d_out, int out_size) {
    const float* v0 = (const float*)d_in[0];
    const float* v1 = (const float*)d_in[1];
    const float* v2 = (const float*)d_in[2];
    const float* s0 = (const float*)d_in[3];
    const float* s1 = (const float*)d_in[4];
    const float* s2 = (const float*)d_in[5];
    const int* conn = (const int*)d_in[6];
    float* out = (float*)d_out;

    static int smem_set = 0;
    if (!smem_set) {
        cudaFuncSetAttribute(mma_gemm, cudaFuncAttributeMaxDynamicSharedMemorySize,
                             NSTG * STAGE);
        smem_set = 1;
    }

    init_kernel<<<4, 1024>>>();
    build_kernel<<<4 * NN, 256>>>(v0, v1, v2, s0, s1, s2, conn);
    mma_gemm<<<dim3(LDC/128, NN/128, 4), 128, NSTG * STAGE>>>();
    scale_kernel<<<dim3((OUTC/4 + 255)/256, 4 * NN), 256>>>(out);
}